// round 7
// baseline (speedup 1.0000x reference)
#include <cuda_runtime.h>

// ---------------------------------------------------------------------------
// Fused 2-layer LSTM (relu cell act), B=128, T=512, F=64, U1=256, U2=128.
// One persistent kernel, 128 CTAs (1/SM via big smem). Each CTA:
//   L1 tile: 16 batch x 16 units, 1 cell/thread (256 thr)
//   L2 tile: 16 batch x 8 units, k-split x2 (shfl-reduced)
// Pipelined: iteration t computes L1 step t then L2 step t-1.
// Activations staged in smem as DUPLICATED f32x2 pairs -> inner loop is
// exactly LDS.64 + LDS.128 + 2x fma.rn.f32x2 per k (FFMA2 pipe floor).
// ---------------------------------------------------------------------------

#define T_STEPS 512
#define BATCH   128
#define FEAT    64
#define U1N     256
#define U2N     128

#define BT      16      // batch rows per CTA
#define NBT     8       // batch tiles
#define U1T     16      // L1 units per CTA
#define NU1T    16      // L1 unit tiles (also = signals per (t,bi) counter)
#define U2T     8       // L2 units per CTA
#define L1K     320     // 64 x-part + 256 h1-part
#define L2K     384     // 256 h1-part + 128 h2-part
#define AROW    449     // sh_a row stride in ulonglong (448 + 1 pad)
#define W2ROW   36      // padded floats per k-row of w2 (32 + 4 pad)

typedef unsigned long long ull;

__device__ float g_h1[T_STEPS][U1N][BATCH];
__device__ float g_h2[T_STEPS][U2N][BATCH];
__device__ int   g_ctr1[T_STEPS * NBT];
__device__ int   g_ctr2[T_STEPS * NBT];

// ---------------------------------------------------------------------------
__device__ __forceinline__ ull packpair(float lo, float hi) {
    ull r; asm("mov.b64 %0, {%1, %2};" : "=l"(r) : "f"(lo), "f"(hi)); return r;
}
__device__ __forceinline__ void unpack2(ull v, float& lo, float& hi) {
    asm("mov.b64 {%0, %1}, %2;" : "=f"(lo), "=f"(hi) : "l"(v));
}
__device__ __forceinline__ ull ffma2(ull a, ull b, ull c) {
    ull d; asm("fma.rn.f32x2 %0, %1, %2, %3;" : "=l"(d) : "l"(a), "l"(b), "l"(c));
    return d;
}
__device__ __forceinline__ ull fadd2(ull a, ull b) {
    ull d; asm("add.rn.f32x2 %0, %1, %2;" : "=l"(d) : "l"(a), "l"(b)); return d;
}
__device__ __forceinline__ float sigm(float z) { return 1.0f / (1.0f + __expf(-z)); }
__device__ __forceinline__ int ld_acquire(const int* p) {
    int v; asm volatile("ld.acquire.gpu.u32 %0, [%1];" : "=r"(v) : "l"(p)); return v;
}

__global__ void reset_kernel() {
    int i = blockIdx.x * blockDim.x + threadIdx.x;
    if (i < T_STEPS * NBT) { g_ctr1[i] = 0; g_ctr2[i] = 0; }
}

// ---------------------------------------------------------------------------
__global__ __launch_bounds__(256, 1)
void lstm_fused(const float* __restrict__ x,  const float* __restrict__ W1,
                const float* __restrict__ U1, const float* __restrict__ b1,
                const float* __restrict__ W2, const float* __restrict__ U2,
                const float* __restrict__ b2, float* __restrict__ out) {
    extern __shared__ float sm[];
    float* sh_w1 = sm;                              // [320][16u][4g] = 20480 f
    float* sh_w2 = sm + L1K * U1T * 4;              // [384][36]      = 13824 f
    ull*   sh_a  = reinterpret_cast<ull*>(sm + L1K * U1T * 4 + L2K * W2ROW);
    // sh_a: [16 b][AROW] dup-pairs; k-layout per row: [x(64) | h1(256) | h2(128)]

    const int tid = threadIdx.x;
    const int ui = blockIdx.x, bi = blockIdx.y;
    const int u10 = ui * U1T, u20 = ui * U2T, b0 = bi * BT;

    const int bl1 = tid & 15, ul1 = tid >> 4;             // L1: 16b x 16u
    const int kh = tid & 1, bl2 = (tid >> 1) & 15, ul2 = tid >> 5;  // L2

    // ---- one-time weight load ----
    for (int i = tid; i < L1K * 64; i += 256) {
        int k = i >> 6, r = i & 63, uu = r >> 2, gi = r & 3;
        sh_w1[i] = (k < FEAT) ? W1[k * 1024 + gi * 256 + u10 + uu]
                              : U1[(k - FEAT) * 1024 + gi * 256 + u10 + uu];
    }
    for (int i = tid; i < L2K * 32; i += 256) {
        int k = i >> 5, r = i & 31, uu = r >> 2, gi = r & 3;
        float v = (k < U1N) ? W2[k * 512 + gi * 128 + u20 + uu]
                            : U2[(k - U1N) * 512 + gi * 128 + u20 + uu];
        sh_w2[k * W2ROW + uu * 4 + gi] = v;
    }
    const ull b1_01 = packpair(b1[u10 + ul1], b1[256 + u10 + ul1]);
    const ull b1_23 = packpair(b1[512 + u10 + ul1], b1[768 + u10 + ul1]);
    const ull b2_01 = kh ? 0ULL : packpair(b2[u20 + ul2], b2[128 + u20 + ul2]);
    const ull b2_23 = kh ? 0ULL : packpair(b2[256 + u20 + ul2], b2[384 + u20 + ul2]);
    float c1 = 0.0f, c2 = 0.0f;
    __syncthreads();

    for (int t = 0; t <= T_STEPS; ++t) {
        // ---- wait for peer tiles of previous steps ----
        if (tid == 0) {
            if (t >= 1) {
                const int* p = &g_ctr1[(t - 1) * NBT + bi];
                while (ld_acquire(p) < NU1T) __nanosleep(32);
            }
            if (t >= 2) {
                const int* p = &g_ctr2[(t - 2) * NBT + bi];
                while (ld_acquire(p) < NU1T) __nanosleep(32);
            }
        }
        __syncthreads();

        // ---- stage activations as duplicated f32x2 pairs ----
        if (t < T_STEPS)
            for (int i = tid; i < BT * FEAT; i += 256) {
                int b = i >> 6, f = i & 63;
                float v = x[((b0 + b) * T_STEPS + t) * FEAT + f];
                sh_a[b * AROW + f] = packpair(v, v);
            }
        if (t >= 1)
            for (int i = tid; i < BT * U1N; i += 256) {
                int b = i & 15, u = i >> 4;
                float v = g_h1[t - 1][u][b0 + b];
                sh_a[b * AROW + FEAT + u] = packpair(v, v);
            }
        if (t >= 2)
            for (int i = tid; i < BT * U2N; i += 256) {
                int b = i & 15, u = i >> 4;
                float v = g_h2[t - 2][u][b0 + b];
                sh_a[b * AROW + FEAT + U1N + u] = packpair(v, v);
            }
        __syncthreads();

        // ---- Layer 1, step t ----
        if (t < T_STEPS) {
            const int kmax = (t == 0) ? FEAT : L1K;
            ull a01 = b1_01, a23 = b1_23;
            const ull* ar = sh_a + bl1 * AROW;
            const ulonglong2* wr = reinterpret_cast<const ulonglong2*>(sh_w1) + ul1;
#pragma unroll 8
            for (int k = 0; k < kmax; ++k) {
                ull av = ar[k];
                ulonglong2 wv = wr[k * 16];
                a01 = ffma2(av, wv.x, a01);
                a23 = ffma2(av, wv.y, a23);
            }
            float zi, zf, zg, zo;
            unpack2(a01, zi, zf);
            unpack2(a23, zg, zo);
            float ig = sigm(zi), fg = sigm(zf);
            float gg = fmaxf(zg, 0.0f), og = sigm(zo);
            c1 = fg * c1 + ig * gg;
            g_h1[t][u10 + ul1][b0 + bl1] = og * fmaxf(c1, 0.0f);
        }
        __syncthreads();
        if (tid == 0 && t < T_STEPS) {
            __threadfence();
            atomicAdd(&g_ctr1[t * NBT + bi], 1);
        }

        // ---- Layer 2, step t-1 (h1[t-1] already resident in sh_a) ----
        if (t >= 1) {
            const int s = t - 1;
            const int kspan = (s == 0) ? 128 : 192;   // per k-half
            ull a01 = b2_01, a23 = b2_23;
            const ull* ar = sh_a + bl2 * AROW + FEAT + kh * kspan;
            const ulonglong2* wr =
                reinterpret_cast<const ulonglong2*>(sh_w2 + kh * kspan * W2ROW) + ul2;
#pragma unroll 8
            for (int j = 0; j < kspan; ++j) {
                ull av = ar[j];
                ulonglong2 wv = wr[j * 9];            // 36 floats = 9 ulonglong2
                a01 = ffma2(av, wv.x, a01);
                a23 = ffma2(av, wv.y, a23);
            }
            // combine the two k-halves across adjacent lanes
            a01 = fadd2(a01, __shfl_xor_sync(0xffffffffu, a01, 1));
            a23 = fadd2(a23, __shfl_xor_sync(0xffffffffu, a23, 1));
            float zi, zf, zg, zo;
            unpack2(a01, zi, zf);
            unpack2(a23, zg, zo);
            float ig = sigm(zi), fg = sigm(zf);
            float gg = fmaxf(zg, 0.0f), og = sigm(zo);
            c2 = fg * c2 + ig * gg;
            float h = og * fmaxf(c2, 0.0f);
            if (kh == 0) {
                if (s == T_STEPS - 1) out[(b0 + bl2) * U2N + u20 + ul2] = h;
                else                  g_h2[s][u20 + ul2][b0 + bl2] = h;
            }
            __syncthreads();
            if (tid == 0) {
                __threadfence();
                atomicAdd(&g_ctr2[s * NBT + bi], 1);
            }
        }
    }
}

// ---------------------------------------------------------------------------
extern "C" void kernel_launch(void* const* d_in, const int* in_sizes, int n_in,
                              void* d_out, int out_size) {
    const float* x  = (const float*)d_in[0];
    const float* W1 = (const float*)d_in[1];
    const float* U1 = (const float*)d_in[2];
    const float* b1 = (const float*)d_in[3];
    const float* W2 = (const float*)d_in[4];
    const float* U2 = (const float*)d_in[5];
    const float* b2 = (const float*)d_in[6];
    float* out = (float*)d_out;

    // smem: w1 20480f + w2 13824f + sh_a 16*449 ull = 137216 + 57472 = 194688 B
    const int smem_bytes = (L1K * U1T * 4 + L2K * W2ROW) * 4 + BT * AROW * 8;
    cudaFuncSetAttribute(lstm_fused, cudaFuncAttributeMaxDynamicSharedMemorySize,
                         smem_bytes);

    reset_kernel<<<4, 1024>>>();
    lstm_fused<<<dim3(NU1T, NBT), 256, smem_bytes>>>(x, W1, U1, b1, W2, U2, b2, out);
}

// round 9
// speedup vs baseline: 1.6385x; 1.6385x over previous
#include <cuda_runtime.h>

// ---------------------------------------------------------------------------
// Fused 2-layer LSTM (relu cell act), B=128, T=512, F=64, U1=256, U2=128.
// 128 persistent CTAs (16 unit-tiles x 8 batch-tiles), 256 threads.
// Register-blocked gate GEMMs: thread tile = 4 batch x 4 gates (1 unit),
// k-split across lanes (L1 x4, L2 x8) reduced via shfl.xor.
// Inner loop per k: 1 LDS.128 (4 acts) + 1 LDS.128 (4 gate w) + 8 fma.f32x2.
// ---------------------------------------------------------------------------

#define T_STEPS 512
#define FEAT    64
#define U1N     256
#define U2N     128
#define BT      16      // batch rows per CTA
#define NBT     8       // batch tiles
#define U1T     16      // L1 units per CTA
#define U2T     8       // L2 units per CTA
#define NUT     16      // unit tiles (signals per counter)

#define AROW    20      // sh_a row stride (floats): conflict-floor, 16B-aligned
#define W1ROW   72      // sh_w1 row stride (floats)
#define W2ROW   36      // sh_w2 row stride (floats)

typedef unsigned long long ull;

// global scratch, consumer-tile-major for coalesced staging
__device__ float g_h1[T_STEPS][NBT][U1N][BT];
__device__ float g_h2[T_STEPS][NBT][U2N][BT];
__device__ int   g_ctr1[T_STEPS * NBT];
__device__ int   g_ctr2[T_STEPS * NBT];

// ---------------------------------------------------------------------------
__device__ __forceinline__ ull ffma2(ull a, ull b, ull c) {
    ull d; asm("fma.rn.f32x2 %0, %1, %2, %3;" : "=l"(d) : "l"(a), "l"(b), "l"(c));
    return d;
}
__device__ __forceinline__ ull fadd2(ull a, ull b) {
    ull d; asm("add.rn.f32x2 %0, %1, %2;" : "=l"(d) : "l"(a), "l"(b)); return d;
}
__device__ __forceinline__ ull dup2(float v) {
    ull d; asm("mov.b64 %0, {%1, %1};" : "=l"(d) : "f"(v)); return d;
}
__device__ __forceinline__ void unpack2(ull v, float& lo, float& hi) {
    asm("mov.b64 {%0, %1}, %2;" : "=f"(lo), "=f"(hi) : "l"(v));
}
__device__ __forceinline__ float sigm(float z) { return 1.0f / (1.0f + __expf(-z)); }
__device__ __forceinline__ int ld_acquire(const int* p) {
    int v; asm volatile("ld.acquire.gpu.u32 %0, [%1];" : "=r"(v) : "l"(p)); return v;
}
__device__ __forceinline__ void red_release(int* p) {
    asm volatile("red.release.gpu.global.add.u32 [%0], 1;" :: "l"(p) : "memory");
}

__global__ void reset_kernel() {
    int i = blockIdx.x * blockDim.x + threadIdx.x;
    if (i < T_STEPS * NBT) { g_ctr1[i] = 0; g_ctr2[i] = 0; }
}

// ---------------------------------------------------------------------------
__global__ __launch_bounds__(256, 1)
void lstm_fused(const float* __restrict__ x,  const float* __restrict__ W1,
                const float* __restrict__ U1, const float* __restrict__ b1,
                const float* __restrict__ W2, const float* __restrict__ U2,
                const float* __restrict__ b2, float* __restrict__ out) {
    extern __shared__ float sm[];
    float* sw1 = sm;                      // [320][72]
    float* sw2 = sm + 320 * W1ROW;        // [384][36]
    float* sa  = sw2 + 384 * W2ROW;       // [448][20]: rows 0-63 x, 64-319 h1, 320-447 h2

    const int tid = threadIdx.x;
    const int ui = blockIdx.x, bi = blockIdx.y;
    const int u10 = ui * U1T, u20 = ui * U2T, b0 = bi * BT;

    // L1 lane mapping: ks1 (k-split 4) | bt1 (4 batch-quads) | uu1 (16 units)
    const int ks1 = tid & 3, bt1 = (tid >> 2) & 3, uu1 = tid >> 4;
    // L2 lane mapping: ks2 (k-split 8) | bt2 (4) | uu2 (8 units)
    const int ks2 = tid & 7, bt2 = (tid >> 3) & 3, uu2 = tid >> 5;

    // ---- one-time weight staging ----
    for (int i = tid; i < 320 * 64; i += 256) {
        int k = i >> 6, r = i & 63, uu = r >> 2, g = r & 3;
        float v = (k < FEAT) ? W1[k * 1024 + g * 256 + u10 + uu]
                             : U1[(k - FEAT) * 1024 + g * 256 + u10 + uu];
        sw1[k * W1ROW + uu * 4 + g] = v;
    }
    for (int i = tid; i < 384 * 32; i += 256) {
        int k = i >> 5, r = i & 31, uu = r >> 2, g = r & 3;
        float v = (k < U1N) ? W2[k * 512 + g * 128 + u20 + uu]
                            : U2[(k - U1N) * 512 + g * 128 + u20 + uu];
        sw2[k * W2ROW + uu * 4 + g] = v;
    }
    float bia1[4], bia2[4];
#pragma unroll
    for (int g = 0; g < 4; ++g) {
        bia1[g] = b1[g * 256 + u10 + uu1];
        bia2[g] = b2[g * 128 + u20 + uu2];
    }
    float c1[4] = {0.f, 0.f, 0.f, 0.f};
    float c2[4] = {0.f, 0.f, 0.f, 0.f};
    __syncthreads();

    for (int t = 0; t <= T_STEPS; ++t) {
        // ---- prefetch x[t] into rows 0-63 (no dependency; overlaps polling) ----
        if (t < T_STEPS) {
            int b = tid >> 4, fc = tid & 15;
            float4 xv = *(const float4*)(x + (((b0 + b) * T_STEPS) + t) * FEAT + fc * 4);
            sa[(fc * 4 + 0) * AROW + b] = xv.x;
            sa[(fc * 4 + 1) * AROW + b] = xv.y;
            sa[(fc * 4 + 2) * AROW + b] = xv.z;
            sa[(fc * 4 + 3) * AROW + b] = xv.w;
        }
        if (tid == 0 && t >= 1) {
            const int* p = &g_ctr1[(t - 1) * NBT + bi];
            while (ld_acquire(p) < NUT) {}
        }
        if (tid == 1 && t >= 2) {
            const int* p = &g_ctr2[(t - 2) * NBT + bi];
            while (ld_acquire(p) < NUT) {}
        }
        __syncthreads();

        // ---- stage h1[t-1] (rows 64-319) and h2[t-2] (rows 320-447), coalesced ----
        if (t >= 1) {
            const float4* src = (const float4*)&g_h1[t - 1][bi][0][0];
#pragma unroll
            for (int q = 0; q < 4; ++q) {
                int L = tid + 256 * q;
                float4 v = src[L];
                int u = L >> 2, c = L & 3;
                *(float4*)(sa + (64 + u) * AROW + c * 4) = v;
            }
        }
        if (t >= 2) {
            const float4* src = (const float4*)&g_h2[t - 2][bi][0][0];
#pragma unroll
            for (int q = 0; q < 2; ++q) {
                int L = tid + 256 * q;
                float4 v = src[L];
                int u = L >> 2, c = L & 3;
                *(float4*)(sa + (320 + u) * AROW + c * 4) = v;
            }
        }
        __syncthreads();

        // ---- Layer 1, step t ----
        if (t < T_STEPS) {
            ull acc[8];
#pragma unroll
            for (int r = 0; r < 8; ++r) acc[r] = 0ULL;
            const int jmax = (t == 0) ? 16 : 80;     // k = j*4 + ks1
            const float* ap = sa + ks1 * AROW + bt1 * 4;
            const float* wp = sw1 + ks1 * W1ROW + uu1 * 4;
#pragma unroll 4
            for (int j = 0; j < jmax; ++j) {
                ulonglong2 av = *(const ulonglong2*)(ap + j * 4 * AROW);
                float4 wv = *(const float4*)(wp + j * 4 * W1ROW);
                ull w0 = dup2(wv.x), w1d = dup2(wv.y), w2d = dup2(wv.z), w3 = dup2(wv.w);
                acc[0] = ffma2(av.x, w0, acc[0]);  acc[1] = ffma2(av.y, w0, acc[1]);
                acc[2] = ffma2(av.x, w1d, acc[2]); acc[3] = ffma2(av.y, w1d, acc[3]);
                acc[4] = ffma2(av.x, w2d, acc[4]); acc[5] = ffma2(av.y, w2d, acc[5]);
                acc[6] = ffma2(av.x, w3, acc[6]);  acc[7] = ffma2(av.y, w3, acc[7]);
            }
            // reduce k-split over lane bits 0-1
#pragma unroll
            for (int r = 0; r < 8; ++r) {
                acc[r] = fadd2(acc[r], __shfl_xor_sync(0xffffffffu, acc[r], 1));
                acc[r] = fadd2(acc[r], __shfl_xor_sync(0xffffffffu, acc[r], 2));
            }
            float h[4];
#pragma unroll
            for (int hf = 0; hf < 2; ++hf) {         // hf=0: b0,b1; hf=1: b2,b3
                float zi[2], zf[2], zg[2], zo[2];
                unpack2(acc[0 + hf], zi[0], zi[1]);
                unpack2(acc[2 + hf], zf[0], zf[1]);
                unpack2(acc[4 + hf], zg[0], zg[1]);
                unpack2(acc[6 + hf], zo[0], zo[1]);
#pragma unroll
                for (int e = 0; e < 2; ++e) {
                    int d = hf * 2 + e;
                    float ig = sigm(zi[e] + bia1[0]);
                    float fg = sigm(zf[e] + bia1[1]);
                    float gg = fmaxf(zg[e] + bia1[2], 0.f);
                    float og = sigm(zo[e] + bia1[3]);
                    c1[d] = fg * c1[d] + ig * gg;
                    h[d] = og * fmaxf(c1[d], 0.f);
                }
            }
            if (ks1 == 0) {
                float4 hv = make_float4(h[0], h[1], h[2], h[3]);
                *(float4*)&g_h1[t][bi][u10 + uu1][bt1 * 4] = hv;
            }
        }

        // ---- Layer 2, step s = t-1 (h1[t-1] already in sa) ----
        if (t >= 1) {
            const int s = t - 1;
            ull acc[8];
#pragma unroll
            for (int r = 0; r < 8; ++r) acc[r] = 0ULL;
            const int jmax = (s == 0) ? 32 : 48;     // k = 64 + j*8 + ks2
            const float* ap = sa + (64 + ks2) * AROW + bt2 * 4;
            const float* wp = sw2 + ks2 * W2ROW + uu2 * 4;
#pragma unroll 4
            for (int j = 0; j < jmax; ++j) {
                ulonglong2 av = *(const ulonglong2*)(ap + j * 8 * AROW);
                float4 wv = *(const float4*)(wp + j * 8 * W2ROW);
                ull w0 = dup2(wv.x), w1d = dup2(wv.y), w2d = dup2(wv.z), w3 = dup2(wv.w);
                acc[0] = ffma2(av.x, w0, acc[0]);  acc[1] = ffma2(av.y, w0, acc[1]);
                acc[2] = ffma2(av.x, w1d, acc[2]); acc[3] = ffma2(av.y, w1d, acc[3]);
                acc[4] = ffma2(av.x, w2d, acc[4]); acc[5] = ffma2(av.y, w2d, acc[5]);
                acc[6] = ffma2(av.x, w3, acc[6]);  acc[7] = ffma2(av.y, w3, acc[7]);
            }
            // reduce k-split over lane bits 0-2
#pragma unroll
            for (int r = 0; r < 8; ++r) {
                acc[r] = fadd2(acc[r], __shfl_xor_sync(0xffffffffu, acc[r], 1));
                acc[r] = fadd2(acc[r], __shfl_xor_sync(0xffffffffu, acc[r], 2));
                acc[r] = fadd2(acc[r], __shfl_xor_sync(0xffffffffu, acc[r], 4));
            }
            float h[4];
#pragma unroll
            for (int hf = 0; hf < 2; ++hf) {
                float zi[2], zf[2], zg[2], zo[2];
                unpack2(acc[0 + hf], zi[0], zi[1]);
                unpack2(acc[2 + hf], zf[0], zf[1]);
                unpack2(acc[4 + hf], zg[0], zg[1]);
                unpack2(acc[6 + hf], zo[0], zo[1]);
#pragma unroll
                for (int e = 0; e < 2; ++e) {
                    int d = hf * 2 + e;
                    float ig = sigm(zi[e] + bia2[0]);
                    float fg = sigm(zf[e] + bia2[1]);
                    float gg = fmaxf(zg[e] + bia2[2], 0.f);
                    float og = sigm(zo[e] + bia2[3]);
                    c2[d] = fg * c2[d] + ig * gg;
                    h[d] = og * fmaxf(c2[d], 0.f);
                }
            }
            if (ks2 == 0) {
                if (s == T_STEPS - 1) {
#pragma unroll
                    for (int d = 0; d < 4; ++d)
                        out[(b0 + bt2 * 4 + d) * U2N + u20 + uu2] = h[d];
                } else {
                    float4 hv = make_float4(h[0], h[1], h[2], h[3]);
                    *(float4*)&g_h2[s][bi][u20 + uu2][bt2 * 4] = hv;
                }
            }
        }

        __syncthreads();
        if (tid == 0 && t < T_STEPS) red_release(&g_ctr1[t * NBT + bi]);
        if (tid == 1 && t >= 1)      red_release(&g_ctr2[(t - 1) * NBT + bi]);
    }
}

// ---------------------------------------------------------------------------
extern "C" void kernel_launch(void* const* d_in, const int* in_sizes, int n_in,
                              void* d_out, int out_size) {
    const float* x  = (const float*)d_in[0];
    const float* W1 = (const float*)d_in[1];
    const float* U1 = (const float*)d_in[2];
    const float* b1 = (const float*)d_in[3];
    const float* W2 = (const float*)d_in[4];
    const float* U2 = (const float*)d_in[5];
    const float* b2 = (const float*)d_in[6];
    float* out = (float*)d_out;

    // smem: (320*72 + 384*36 + 448*20) * 4B = 183296 B -> 1 CTA/SM, 128 CTAs
    const int smem_bytes = (320 * W1ROW + 384 * W2ROW + 448 * AROW) * 4;
    cudaFuncSetAttribute(lstm_fused, cudaFuncAttributeMaxDynamicSharedMemorySize,
                         smem_bytes);

    reset_kernel<<<4, 1024>>>();
    lstm_fused<<<dim3(NUT, NBT), 256, smem_bytes>>>(x, W1, U1, b1, W2, U2, b2, out);
}

// round 12
// speedup vs baseline: 2.6050x; 1.5898x over previous
#include <cuda_runtime.h>

// ---------------------------------------------------------------------------
// Fused 2-layer LSTM (relu cell act), B=128, T=512, F=64, U1=256, U2=128.
// 128 persistent CTAs (16 unit-tiles x 8 batch-tiles), 256 threads, 1 CTA/SM.
// L1: thread = (upos1 16u, ks1 16 k-splits), full 16-batch tile in regs,
//     L1 weights REGISTER-RESIDENT (80 floats) -> a-only LDS, 1 B/MAC.
// L2: thread = (bh2, upos2 8u, ks2 16 k-splits), 8b x 4g tile, w from smem.
// k-split reduced via recursive-halving shfl; each lane lands on its own
// (b,u) cell -> scalar cell state, lane-parallel epilogue.
// ---------------------------------------------------------------------------

#define T_STEPS 512
#define FEAT    64
#define U1N     256
#define U2N     128
#define BT      16
#define NBT     8
#define NUT     16

#define AROW    34      // sa row stride (floats): banks 2*ks -> conflict-free
#define W2ROW   34      // sw2 row stride (floats), layout [k][g*8 + u]

typedef unsigned long long ull;

__device__ float g_h1[T_STEPS][NBT][U1N][BT];
__device__ float g_h2[T_STEPS][NBT][U2N][BT];
__device__ int   g_ctr1[T_STEPS * NBT];
__device__ int   g_ctr2[T_STEPS * NBT];

// ---------------------------------------------------------------------------
__device__ __forceinline__ ull ffma2(ull a, ull b, ull c) {
    ull d; asm("fma.rn.f32x2 %0, %1, %2, %3;" : "=l"(d) : "l"(a), "l"(b), "l"(c));
    return d;
}
__device__ __forceinline__ ull fadd2(ull a, ull b) {
    ull d; asm("add.rn.f32x2 %0, %1, %2;" : "=l"(d) : "l"(a), "l"(b)); return d;
}
__device__ __forceinline__ ull dup2(float v) {
    ull d; asm("mov.b64 %0, {%1, %1};" : "=l"(d) : "f"(v)); return d;
}
__device__ __forceinline__ void unpack2(ull v, float& lo, float& hi) {
    asm("mov.b64 {%0, %1}, %2;" : "=f"(lo), "=f"(hi) : "l"(v));
}
__device__ __forceinline__ float sigm(float z) { return 1.0f / (1.0f + __expf(-z)); }
__device__ __forceinline__ int ld_acquire(const int* p) {
    int v; asm volatile("ld.acquire.gpu.u32 %0, [%1];" : "=r"(v) : "l"(p)); return v;
}
__device__ __forceinline__ void red_release(int* p) {
    asm volatile("red.release.gpu.global.add.u32 [%0], 1;" :: "l"(p) : "memory");
}
__device__ __forceinline__ ull shx(ull v, int d) {
    return __shfl_xor_sync(0xffffffffu, v, d);
}

__global__ void reset_kernel() {
    int i = blockIdx.x * blockDim.x + threadIdx.x;
    if (i < T_STEPS * NBT) { g_ctr1[i] = 0; g_ctr2[i] = 0; }
}

// ---------------------------------------------------------------------------
__global__ __launch_bounds__(256, 1)
void lstm_fused(const float* __restrict__ x,  const float* __restrict__ W1,
                const float* __restrict__ U1, const float* __restrict__ b1,
                const float* __restrict__ W2, const float* __restrict__ U2,
                const float* __restrict__ b2, float* __restrict__ out) {
    extern __shared__ float sm[];
    float* sw2 = sm;                    // [384][34], layout [k][g*8+u]
    float* sa  = sm + 384 * W2ROW;      // [448][34]: 0-63 x, 64-319 h1, 320-447 h2

    const int tid = threadIdx.x;
    const int ui = blockIdx.x, bi = blockIdx.y;
    const int u10 = ui * 16, u20 = ui * 8, b0 = bi * BT;

    const int ks1 = tid & 15, upos1 = tid >> 4;
    const int ks2 = tid & 15, upos2 = (tid >> 4) & 7, bh2 = tid >> 7;

    // ---- L1 weights -> registers (k = j*16 + ks1, gates i,f,g,o) ----
    float w1r[80];
#pragma unroll
    for (int j = 0; j < 20; ++j)
#pragma unroll
        for (int g = 0; g < 4; ++g) {
            int k = j * 16 + ks1;
            w1r[j * 4 + g] = (j < 4)
                ? W1[k * 1024 + g * 256 + u10 + upos1]
                : U1[(k - 64) * 1024 + g * 256 + u10 + upos1];
        }
    // ---- L2 weights -> smem ----
    for (int i = tid; i < 384 * 32; i += 256) {
        int k = i >> 5, r = i & 31, g = r >> 3, uu = r & 7;
        float v = (k < U1N) ? W2[k * 512 + g * 128 + u20 + uu]
                            : U2[(k - U1N) * 512 + g * 128 + u20 + uu];
        sw2[k * W2ROW + g * 8 + uu] = v;
    }
    // ---- zero h rows (t=0 / s=0 use zeros -> uniform full-k loops) ----
    for (int i = tid; i < 384 * AROW; i += 256) sa[64 * AROW + i] = 0.f;

    float bia1[4], bia2[4];
#pragma unroll
    for (int g = 0; g < 4; ++g) {
        bia1[g] = b1[g * 256 + u10 + upos1];
        bia2[g] = b2[g * 128 + u20 + upos2];
    }
    float c1 = 0.f, c2 = 0.f;
    __syncthreads();

    for (int t = 0; t <= T_STEPS; ++t) {
        // ---- x prefetch (LDG overlaps polling) ----
        float4 xv = make_float4(0.f, 0.f, 0.f, 0.f);
        if (t < T_STEPS)
            xv = *(const float4*)(x + ((size_t)(b0 + (tid >> 4)) * T_STEPS + t) * FEAT
                                  + (tid & 15) * 4);
        if (tid == 0 && t >= 1) {
            const int* p = &g_ctr1[(t - 1) * NBT + bi];
            while (ld_acquire(p) < NUT) {}
        }
        if (tid == 1 && t >= 2) {
            const int* p = &g_ctr2[(t - 2) * NBT + bi];
            while (ld_acquire(p) < NUT) {}
        }
        __syncthreads();

        // ---- stage: x rows 0-63, h1[t-1] rows 64-319, h2[t-2] rows 320-447 ----
        if (t < T_STEPS) {
            int fb = tid & 15, bb = tid >> 4;
            sa[(fb * 4 + 0) * AROW + bb] = xv.x;
            sa[(fb * 4 + 1) * AROW + bb] = xv.y;
            sa[(fb * 4 + 2) * AROW + bb] = xv.z;
            sa[(fb * 4 + 3) * AROW + bb] = xv.w;
        }
        if (t >= 1) {
            const float4* src = (const float4*)&g_h1[t - 1][bi][0][0];
#pragma unroll
            for (int q = 0; q < 4; ++q) {
                int L = tid + 256 * q;
                float4 v = src[L];
                int u = L >> 2, cc = (L & 3) * 4;
                float* d = sa + (64 + u) * AROW + cc;
                *(float2*)d = make_float2(v.x, v.y);
                *(float2*)(d + 2) = make_float2(v.z, v.w);
            }
        }
        if (t >= 2) {
            const float4* src = (const float4*)&g_h2[t - 2][bi][0][0];
#pragma unroll
            for (int q = 0; q < 2; ++q) {
                int L = tid + 256 * q;
                float4 v = src[L];
                int u = L >> 2, cc = (L & 3) * 4;
                float* d = sa + (320 + u) * AROW + cc;
                *(float2*)d = make_float2(v.x, v.y);
                *(float2*)(d + 2) = make_float2(v.z, v.w);
            }
        }
        __syncthreads();

        // ================= Layer 1, step t =================
        if (t < T_STEPS) {
            ull A[32];
#pragma unroll
            for (int r = 0; r < 32; ++r) A[r] = 0ULL;
            const float* ar = sa + ks1 * AROW;
#pragma unroll
            for (int j = 0; j < 20; ++j) {
                ull av[8];
#pragma unroll
                for (int bp = 0; bp < 8; ++bp)
                    av[bp] = *(const ull*)(ar + j * (16 * AROW) + bp * 2);
#pragma unroll
                for (int g = 0; g < 4; ++g) {
                    ull wd = dup2(w1r[j * 4 + g]);
#pragma unroll
                    for (int bp = 0; bp < 8; ++bp)
                        A[g * 8 + bp] = ffma2(av[bp], wd, A[g * 8 + bp]);
                }
            }
            // recursive-halving reduce over ks1; lane ends on bp = ks1>>1
            const bool c8 = (ks1 & 8), c4 = (ks1 & 4), c2f = (ks1 & 2);
            ull B[16];
#pragma unroll
            for (int g = 0; g < 4; ++g)
#pragma unroll
                for (int p = 0; p < 4; ++p) {
                    ull kp = c8 ? A[g * 8 + 4 + p] : A[g * 8 + p];
                    ull sd = c8 ? A[g * 8 + p]     : A[g * 8 + 4 + p];
                    B[g * 4 + p] = fadd2(kp, shx(sd, 8));
                }
            ull C[8];
#pragma unroll
            for (int g = 0; g < 4; ++g)
#pragma unroll
                for (int p = 0; p < 2; ++p) {
                    ull kp = c4 ? B[g * 4 + 2 + p] : B[g * 4 + p];
                    ull sd = c4 ? B[g * 4 + p]     : B[g * 4 + 2 + p];
                    C[g * 2 + p] = fadd2(kp, shx(sd, 4));
                }
            ull D[4];
#pragma unroll
            for (int g = 0; g < 4; ++g) {
                ull kp = c2f ? C[g * 2 + 1] : C[g * 2];
                ull sd = c2f ? C[g * 2]     : C[g * 2 + 1];
                D[g] = fadd2(kp, shx(sd, 2));
            }
#pragma unroll
            for (int g = 0; g < 4; ++g) D[g] = fadd2(D[g], shx(D[g], 1));

            const int e = ks1 & 1;
            float z[4];
#pragma unroll
            for (int g = 0; g < 4; ++g) {
                float lo, hi; unpack2(D[g], lo, hi);
                z[g] = e ? hi : lo;
            }
            float ig = sigm(z[0] + bia1[0]);
            float fg = sigm(z[1] + bia1[1]);
            float gg = fmaxf(z[2] + bia1[2], 0.f);
            float og = sigm(z[3] + bia1[3]);
            c1 = fg * c1 + ig * gg;
            g_h1[t][bi][u10 + upos1][ks1] = og * fmaxf(c1, 0.f);
        }

        // ================= Layer 2, step s = t-1 =================
        if (t >= 1) {
            const int s = t - 1;
            ull A2[16];
#pragma unroll
            for (int r = 0; r < 16; ++r) A2[r] = 0ULL;
            const float* ar2 = sa + (64 + ks2) * AROW + bh2 * 8;
            const float* wr2 = sw2 + ks2 * W2ROW + upos2;
#pragma unroll
            for (int j = 0; j < 24; ++j) {
                ull av[4];
#pragma unroll
                for (int bp = 0; bp < 4; ++bp)
                    av[bp] = *(const ull*)(ar2 + j * (16 * AROW) + bp * 2);
#pragma unroll
                for (int g = 0; g < 4; ++g) {
                    ull wd = dup2(wr2[j * (16 * W2ROW) + g * 8]);
#pragma unroll
                    for (int bp = 0; bp < 4; ++bp)
                        A2[g * 4 + bp] = ffma2(av[bp], wd, A2[g * 4 + bp]);
                }
            }
            // reduce: halve bp by bits 2,1; full exchange bits 3,0
            const bool d4 = (ks2 & 4), d2 = (ks2 & 2);
            ull B2[8];
#pragma unroll
            for (int g = 0; g < 4; ++g)
#pragma unroll
                for (int p = 0; p < 2; ++p) {
                    ull kp = d4 ? A2[g * 4 + 2 + p] : A2[g * 4 + p];
                    ull sd = d4 ? A2[g * 4 + p]     : A2[g * 4 + 2 + p];
                    B2[g * 2 + p] = fadd2(kp, shx(sd, 4));
                }
            ull C2[4];
#pragma unroll
            for (int g = 0; g < 4; ++g) {
                ull kp = d2 ? B2[g * 2 + 1] : B2[g * 2];
                ull sd = d2 ? B2[g * 2]     : B2[g * 2 + 1];
                C2[g] = fadd2(kp, shx(sd, 2));
            }
#pragma unroll
            for (int g = 0; g < 4; ++g) C2[g] = fadd2(C2[g], shx(C2[g], 8));
#pragma unroll
            for (int g = 0; g < 4; ++g) C2[g] = fadd2(C2[g], shx(C2[g], 1));

            const int e2 = ks2 & 1;
            float z[4];
#pragma unroll
            for (int g = 0; g < 4; ++g) {
                float lo, hi; unpack2(C2[g], lo, hi);
                z[g] = e2 ? hi : lo;
            }
            float ig = sigm(z[0] + bia2[0]);
            float fg = sigm(z[1] + bia2[1]);
            float gg = fmaxf(z[2] + bia2[2], 0.f);
            float og = sigm(z[3] + bia2[3]);
            c2 = fg * c2 + ig * gg;
            float h = og * fmaxf(c2, 0.f);
            if (!(ks2 & 8)) {
                int b = bh2 * 8 + ks2;     // ks2 < 8 here
                if (s == T_STEPS - 1) out[(b0 + b) * U2N + u20 + upos2] = h;
                else                  g_h2[s][bi][u20 + upos2][b] = h;
            }
        }

        __syncthreads();
        if (tid == 0 && t < T_STEPS) red_release(&g_ctr1[t * NBT + bi]);
        if (tid == 1 && t >= 1)      red_release(&g_ctr2[(t - 1) * NBT + bi]);
    }
}

// ---------------------------------------------------------------------------
extern "C" void kernel_launch(void* const* d_in, const int* in_sizes, int n_in,
                              void* d_out, int out_size) {
    const float* x  = (const float*)d_in[0];
    const float* W1 = (const float*)d_in[1];
    const float* U1 = (const float*)d_in[2];
    const float* b1 = (const float*)d_in[3];
    const float* W2 = (const float*)d_in[4];
    const float* U2 = (const float*)d_in[5];
    const float* b2 = (const float*)d_in[6];
    float* out = (float*)d_out;

    // needed: (384*34 + 448*34)*4 = 113152 B; request 120KB so 2 CTAs/SM
    // (240KB) exceed the 228KB SM limit -> guaranteed 1 CTA/SM co-residency.
    const int smem_bytes = 120 * 1024;
    cudaFuncSetAttribute(lstm_fused, cudaFuncAttributeMaxDynamicSharedMemorySize,
                         smem_bytes);

    reset_kernel<<<4, 1024>>>();
    lstm_fused<<<dim3(NUT, NBT), 256, smem_bytes>>>(x, W1, U1, b1, W2, U2, b2, out);
}